// round 1
// baseline (speedup 1.0000x reference)
#include <cuda_runtime.h>
#include <cuda_bf16.h>
#include <math.h>

// Problem shapes (fixed per reference)
#define B_ 16
#define S_ 512
#define E_ 1024
#define Q_ 8
#define L_ 4

#define BS_ROWS (B_ * S_)            // 8192
#define OUT_ELEMS (B_ * S_ * E_)     // 8388608
#define ATTN_ELEMS (B_ * S_ * S_)    // 4194304

// ---------------------------------------------------------------------------
// Scratch (device globals: allocation-free rule)
// ---------------------------------------------------------------------------
__device__ float g_states[BS_ROWS * Q_ * 4];   // [b*s][q][{ar,ai,br,bi}]  1 MB
__device__ float g_V[B_ * S_ * E_];            // 32 MB
__device__ float g_T[B_ * S_ * E_];            // 32 MB (attn @ V)

// ---------------------------------------------------------------------------
// Kernel 1: quantum_input = X@Wq + bq, then RY/RZ recursion -> product state
// one block per token row, 8 warps = 8 qubits
// ---------------------------------------------------------------------------
__global__ void qstate_kernel(const float* __restrict__ X,
                              const float* __restrict__ Wq,
                              const float* __restrict__ bq,
                              const float* __restrict__ theta)
{
    int row  = blockIdx.x;               // b*512 + s
    int warp = threadIdx.x >> 5;
    int lane = threadIdx.x & 31;
    int q = warp;                        // 8 warps
    const float* x = X + (size_t)row * E_;

    float acc = 0.f;
    for (int e = lane; e < E_; e += 32)
        acc += x[e] * Wq[e * Q_ + q];
    #pragma unroll
    for (int off = 16; off; off >>= 1)
        acc += __shfl_xor_sync(0xffffffffu, acc, off);

    if (lane == 0) {
        float ang = acc + bq[q];
        float ar = cosf(0.5f * ang), ai = 0.f;
        float br = sinf(0.5f * ang), bi = 0.f;
        #pragma unroll
        for (int l = 0; l < L_; l++) {
            float t0 = 0.5f * theta[(l * Q_ + q) * 2 + 0];
            float t1 = 0.5f * theta[(l * Q_ + q) * 2 + 1];
            float c = cosf(t0), s = sinf(t0);
            float nar = c * ar - s * br, nai = c * ai - s * bi;
            float nbr = s * ar + c * br, nbi = s * ai + c * bi;
            // a *= e^{-i t1};  b *= e^{+i t1}
            float cp = cosf(t1), sp = sinf(t1);
            ar = nar * cp + nai * sp;  ai = nai * cp - nar * sp;
            br = nbr * cp - nbi * sp;  bi = nbi * cp + nbr * sp;
        }
        float* st = g_states + (size_t)row * (Q_ * 4) + q * 4;
        st[0] = ar; st[1] = ai; st[2] = br; st[3] = bi;
    }
}

// ---------------------------------------------------------------------------
// SGEMM: C = A(M,K) @ B(K,N) [+ bias(N)], row-major, 128x128x8 tile,
// 256 threads, 8x8 per-thread microtile, float4 gmem/smem traffic.
// Batched via blockIdx.z and element strides. Shapes are multiples of tiles.
// ---------------------------------------------------------------------------
__global__ __launch_bounds__(256)
void sgemm128(const float* __restrict__ A, const float* __restrict__ Bm,
              const float* __restrict__ bias, float* __restrict__ C,
              int M, int N, int K,
              long long strideA, long long strideB, long long strideC)
{
    const int BM = 128, BN = 128, BK = 8, TM = 8, TN = 8;
    __shared__ float As[BK][BM];
    __shared__ float Bs[BK][BN];

    A  += (long long)blockIdx.z * strideA + (long long)blockIdx.y * BM * K;
    Bm += (long long)blockIdx.z * strideB + (long long)blockIdx.x * BN;
    C  += (long long)blockIdx.z * strideC + (long long)blockIdx.y * BM * N
        + (long long)blockIdx.x * BN;

    int tid = threadIdx.x;
    int innerRowA = tid >> 1,  innerColA = (tid & 1) * 4;
    int innerRowB = tid >> 5,  innerColB = (tid & 31) * 4;
    int threadRow = tid >> 4,  threadCol = tid & 15;

    float acc[TM][TN] = {};
    float regA[TM], regB[TN];

    for (int k0 = 0; k0 < K; k0 += BK) {
        float4 ta = *(const float4*)(A + (long long)innerRowA * K + innerColA);
        As[innerColA + 0][innerRowA] = ta.x;
        As[innerColA + 1][innerRowA] = ta.y;
        As[innerColA + 2][innerRowA] = ta.z;
        As[innerColA + 3][innerRowA] = ta.w;
        *(float4*)&Bs[innerRowB][innerColB] =
            *(const float4*)(Bm + (long long)innerRowB * N + innerColB);
        __syncthreads();
        A += BK; Bm += (long long)BK * N;

        #pragma unroll
        for (int k = 0; k < BK; k++) {
            #pragma unroll
            for (int m = 0; m < TM; m++) regA[m] = As[k][threadRow * TM + m];
            #pragma unroll
            for (int n = 0; n < TN; n++) regB[n] = Bs[k][threadCol * TN + n];
            #pragma unroll
            for (int m = 0; m < TM; m++)
                #pragma unroll
                for (int n = 0; n < TN; n++)
                    acc[m][n] = fmaf(regA[m], regB[n], acc[m][n]);
        }
        __syncthreads();
    }

    #pragma unroll
    for (int m = 0; m < TM; m++) {
        int r = threadRow * TM + m;
        #pragma unroll
        for (int n = 0; n < TN; n += 4) {
            int c = threadCol * TN + n;
            float4 v;
            v.x = acc[m][n + 0]; v.y = acc[m][n + 1];
            v.z = acc[m][n + 2]; v.w = acc[m][n + 3];
            if (bias) {
                int gc = blockIdx.x * BN + c;
                v.x += bias[gc + 0]; v.y += bias[gc + 1];
                v.z += bias[gc + 2]; v.w += bias[gc + 3];
            }
            *(float4*)(C + (long long)r * N + c) = v;
        }
    }
}

// ---------------------------------------------------------------------------
// Kernel 3: fidelity kernel matrix + interference + row softmax -> attn
// one block (256 thr) per (b, i) row; states for batch b are 64 KB (L1-warm)
// ---------------------------------------------------------------------------
__global__ __launch_bounds__(256)
void attn_kernel(const float* __restrict__ phi, float* __restrict__ attn)
{
    int row = blockIdx.x;                 // b*512 + i
    int b = row >> 9, i = row & 511;
    const float* st_b = g_states + (size_t)b * S_ * (Q_ * 4);

    __shared__ float si[Q_ * 4];
    __shared__ float sK[S_];
    __shared__ float red[8];

    if (threadIdx.x < Q_ * 4)
        si[threadIdx.x] = st_b[(size_t)i * (Q_ * 4) + threadIdx.x];
    __syncthreads();

    float phii = phi[i];

    for (int j = threadIdx.x; j < S_; j += 256) {
        const float* sj = st_b + (size_t)j * (Q_ * 4);
        float Kv = 1.f;
        #pragma unroll
        for (int q = 0; q < Q_; q++) {
            float air = si[q*4+0], aii = si[q*4+1], bir = si[q*4+2], bii = si[q*4+3];
            float ajr = sj[q*4+0], aji = sj[q*4+1], bjr = sj[q*4+2], bji = sj[q*4+3];
            // ip = conj(a_i)a_j + conj(b_i)b_j
            float re = air*ajr + aii*aji + bir*bjr + bii*bji;
            float im = air*aji - aii*ajr + bir*bji - bii*bjr;
            Kv *= re*re + im*im;
        }
        sK[j] = Kv + cosf(phii - phi[j]);
    }
    __syncthreads();

    // row max
    float m = -1e30f;
    for (int j = threadIdx.x; j < S_; j += 256) m = fmaxf(m, sK[j]);
    #pragma unroll
    for (int off = 16; off; off >>= 1) m = fmaxf(m, __shfl_xor_sync(~0u, m, off));
    if ((threadIdx.x & 31) == 0) red[threadIdx.x >> 5] = m;
    __syncthreads();
    if (threadIdx.x < 8) {
        float v = red[threadIdx.x];
        #pragma unroll
        for (int off = 4; off; off >>= 1) v = fmaxf(v, __shfl_xor_sync(0xffu, v, off));
        if (threadIdx.x == 0) red[0] = v;
    }
    __syncthreads();
    m = red[0];
    __syncthreads();

    // exp + sum
    float sum = 0.f;
    for (int j = threadIdx.x; j < S_; j += 256) {
        float e = expf(sK[j] - m);
        sK[j] = e;
        sum += e;
    }
    #pragma unroll
    for (int off = 16; off; off >>= 1) sum += __shfl_xor_sync(~0u, sum, off);
    if ((threadIdx.x & 31) == 0) red[threadIdx.x >> 5] = sum;
    __syncthreads();
    if (threadIdx.x < 8) {
        float v = red[threadIdx.x];
        #pragma unroll
        for (int off = 4; off; off >>= 1) v += __shfl_xor_sync(0xffu, v, off);
        if (threadIdx.x == 0) red[0] = v;
    }
    __syncthreads();
    float inv = 1.f / red[0];

    float* arow = attn + (size_t)row * S_;
    for (int j = threadIdx.x; j < S_; j += 256)
        arow[j] = sK[j] * inv;
}

// ---------------------------------------------------------------------------
// launch
// ---------------------------------------------------------------------------
extern "C" void kernel_launch(void* const* d_in, const int* in_sizes, int n_in,
                              void* d_out, int out_size)
{
    const float* X     = (const float*)d_in[0];
    const float* Wq    = (const float*)d_in[1];
    const float* bq    = (const float*)d_in[2];
    const float* Wv    = (const float*)d_in[3];
    const float* bv    = (const float*)d_in[4];
    const float* Wo    = (const float*)d_in[5];
    const float* bo    = (const float*)d_in[6];
    const float* theta = (const float*)d_in[7];
    const float* phi   = (const float*)d_in[8];

    float* out  = (float*)d_out;                 // [B,S,E]
    float* attn = (float*)d_out + OUT_ELEMS;     // [B,S,S]

    float* Vbuf;  cudaGetSymbolAddress((void**)&Vbuf, g_V);
    float* Tbuf;  cudaGetSymbolAddress((void**)&Tbuf, g_T);

    (void)in_sizes; (void)n_in; (void)out_size;

    // 1) qubit states
    qstate_kernel<<<BS_ROWS, 256>>>(X, Wq, bq, theta);

    // 2) V = X @ Wv + bv   (8192 x 1024 x 1024)
    {
        dim3 grid(E_ / 128, BS_ROWS / 128, 1);
        sgemm128<<<grid, 256>>>(X, Wv, bv, Vbuf, BS_ROWS, E_, E_, 0, 0, 0);
    }

    // 3) kernel matrix + softmax -> attn (written straight into d_out)
    attn_kernel<<<BS_ROWS, 256>>>(phi, attn);

    // 4) T[b] = attn[b] @ V[b]   (batched 512 x 1024 x 512)
    {
        dim3 grid(E_ / 128, S_ / 128, B_);
        sgemm128<<<grid, 256>>>(attn, Vbuf, nullptr, Tbuf, S_, E_, S_,
                                (long long)S_ * S_, (long long)S_ * E_,
                                (long long)S_ * E_);
    }

    // 5) out = T @ Wo + bo   (8192 x 1024 x 1024)
    {
        dim3 grid(E_ / 128, BS_ROWS / 128, 1);
        sgemm128<<<grid, 256>>>(Tbuf, Wo, bo, out, BS_ROWS, E_, E_, 0, 0, 0);
    }
}

// round 3
// speedup vs baseline: 2.4532x; 2.4532x over previous
#include <cuda_runtime.h>
#include <cuda_bf16.h>
#include <stdint.h>
#include <math.h>

// Problem shapes (fixed per reference)
#define B_ 16
#define S_ 512
#define E_ 1024
#define Q_ 8
#define L_ 4

#define BS_ROWS (B_ * S_)            // 8192
#define OUT_ELEMS (B_ * S_ * E_)     // 8388608
#define ATTN_ELEMS (B_ * S_ * S_)    // 4194304

// ---------------------------------------------------------------------------
// Scratch (device globals: allocation-free rule). 16B-aligned for uint4 I/O.
// ---------------------------------------------------------------------------
__device__ __align__(16) float g_states[BS_ROWS * Q_ * 4];

__device__ __align__(16) __nv_bfloat16 g_Xh[BS_ROWS * E_];
__device__ __align__(16) __nv_bfloat16 g_Xl[BS_ROWS * E_];
__device__ __align__(16) __nv_bfloat16 g_Wvh[E_ * E_];
__device__ __align__(16) __nv_bfloat16 g_Wvl[E_ * E_];
__device__ __align__(16) __nv_bfloat16 g_Woh[E_ * E_];
__device__ __align__(16) __nv_bfloat16 g_Wol[E_ * E_];
__device__ __align__(16) __nv_bfloat16 g_Vh[B_ * S_ * E_];
__device__ __align__(16) __nv_bfloat16 g_Vl[B_ * S_ * E_];
__device__ __align__(16) __nv_bfloat16 g_Ath[B_ * S_ * S_];
__device__ __align__(16) __nv_bfloat16 g_Atl[B_ * S_ * S_];
__device__ __align__(16) __nv_bfloat16 g_Th[B_ * S_ * E_];
__device__ __align__(16) __nv_bfloat16 g_Tl[B_ * S_ * E_];

__device__ __forceinline__ void split2(float v, __nv_bfloat16 &h, __nv_bfloat16 &l)
{
    h = __float2bfloat16(v);
    l = __float2bfloat16(v - __bfloat162float(h));
}

// ---------------------------------------------------------------------------
// Split fp32 -> bf16 hi/lo (vectorized)
// ---------------------------------------------------------------------------
__global__ void split_fp32_kernel(const float* __restrict__ src,
                                  __nv_bfloat16* __restrict__ h,
                                  __nv_bfloat16* __restrict__ l, int n)
{
    int i = (blockIdx.x * blockDim.x + threadIdx.x) * 4;
    if (i >= n) return;
    float4 v = *(const float4*)(src + i);
    __nv_bfloat16 h0, h1, h2, h3, l0, l1, l2, l3;
    split2(v.x, h0, l0);
    split2(v.y, h1, l1);
    split2(v.z, h2, l2);
    split2(v.w, h3, l3);
    __nv_bfloat162 p;
    p.x = h0; p.y = h1; *(__nv_bfloat162*)(h + i)     = p;
    p.x = h2; p.y = h3; *(__nv_bfloat162*)(h + i + 2) = p;
    p.x = l0; p.y = l1; *(__nv_bfloat162*)(l + i)     = p;
    p.x = l2; p.y = l3; *(__nv_bfloat162*)(l + i + 2) = p;
}

// ---------------------------------------------------------------------------
// Kernel 1: quantum_input = X@Wq + bq, then RY/RZ recursion -> product state
// ---------------------------------------------------------------------------
__global__ void qstate_kernel(const float* __restrict__ X,
                              const float* __restrict__ Wq,
                              const float* __restrict__ bq,
                              const float* __restrict__ theta)
{
    int row  = blockIdx.x;
    int warp = threadIdx.x >> 5;
    int lane = threadIdx.x & 31;
    int q = warp;
    const float* x = X + (size_t)row * E_;

    float acc = 0.f;
    for (int e = lane; e < E_; e += 32)
        acc += x[e] * Wq[e * Q_ + q];
    for (int off = 16; off; off >>= 1)
        acc += __shfl_xor_sync(0xffffffffu, acc, off);

    if (lane == 0) {
        float ang = acc + bq[q];
        float ar = cosf(0.5f * ang);
        float ai = 0.f;
        float br = sinf(0.5f * ang);
        float bi = 0.f;
        for (int l = 0; l < L_; l++) {
            float t0 = 0.5f * theta[(l * Q_ + q) * 2 + 0];
            float t1 = 0.5f * theta[(l * Q_ + q) * 2 + 1];
            float c = cosf(t0), s = sinf(t0);
            float nar = c * ar - s * br, nai = c * ai - s * bi;
            float nbr = s * ar + c * br, nbi = s * ai + c * bi;
            float cp = cosf(t1), sp = sinf(t1);
            ar = nar * cp + nai * sp;
            ai = nai * cp - nar * sp;
            br = nbr * cp - nbi * sp;
            bi = nbi * cp + nbr * sp;
        }
        float* st = g_states + (size_t)row * (Q_ * 4) + q * 4;
        st[0] = ar; st[1] = ai; st[2] = br; st[3] = bi;
    }
}

// ---------------------------------------------------------------------------
// mma.sync helpers
// ---------------------------------------------------------------------------
__device__ __forceinline__ void ldmat_x4(unsigned int* r, const __nv_bfloat16* p)
{
    unsigned int a = (unsigned int)__cvta_generic_to_shared(p);
    asm volatile("ldmatrix.sync.aligned.m8n8.x4.shared.b16 {%0,%1,%2,%3}, [%4];"
                 : "=r"(r[0]), "=r"(r[1]), "=r"(r[2]), "=r"(r[3]) : "r"(a));
}

__device__ __forceinline__ void ldmat_x4t(unsigned int* r, const __nv_bfloat16* p)
{
    unsigned int a = (unsigned int)__cvta_generic_to_shared(p);
    asm volatile("ldmatrix.sync.aligned.m8n8.x4.trans.shared.b16 {%0,%1,%2,%3}, [%4];"
                 : "=r"(r[0]), "=r"(r[1]), "=r"(r[2]), "=r"(r[3]) : "r"(a));
}

__device__ __forceinline__ void mma16816(float* d, const unsigned int* a, const unsigned int* b)
{
    asm volatile(
        "mma.sync.aligned.m16n8k16.row.col.f32.bf16.bf16.f32 "
        "{%0,%1,%2,%3}, {%4,%5,%6,%7}, {%8,%9}, {%0,%1,%2,%3};"
        : "+f"(d[0]), "+f"(d[1]), "+f"(d[2]), "+f"(d[3])
        : "r"(a[0]), "r"(a[1]), "r"(a[2]), "r"(a[3]), "r"(b[0]), "r"(b[1]));
}

// ---------------------------------------------------------------------------
// bf16-split GEMM: C = (Ah+Al)(Bh+Bl) ~= AhBh + AhBl + AlBh
// A row-major [M,K], B row-major [K,N]. 128x128x32 tile, 256 thr (8 warps).
// Optional fp32 output (+bias) and/or bf16 hi/lo split output.
// ---------------------------------------------------------------------------
__global__ __launch_bounds__(256)
void gemm_bf16s(const __nv_bfloat16* __restrict__ Ah, const __nv_bfloat16* __restrict__ Al,
                const __nv_bfloat16* __restrict__ Bh, const __nv_bfloat16* __restrict__ Bl,
                const float* __restrict__ bias,
                float* __restrict__ Cf,
                __nv_bfloat16* __restrict__ Ch, __nv_bfloat16* __restrict__ Cl,
                int M, int N, int K,
                long long sA, long long sB, long long sC)
{
    __shared__ __align__(16) __nv_bfloat16 sAh[128][40];
    __shared__ __align__(16) __nv_bfloat16 sAl[128][40];
    __shared__ __align__(16) __nv_bfloat16 sBh[32][136];
    __shared__ __align__(16) __nv_bfloat16 sBl[32][136];

    const int tid  = threadIdx.x;
    const int warp = tid >> 5;
    const int lane = tid & 31;
    const int warp_m = warp & 1;           // 2 x 4 warp grid
    const int warp_n = warp >> 1;
    const int m_base = warp_m * 64;
    const int n_base = warp_n * 32;

    const long long z = blockIdx.z;
    const __nv_bfloat16* Ahp = Ah + z * sA + (long long)blockIdx.y * 128 * K;
    const __nv_bfloat16* Alp = Al + z * sA + (long long)blockIdx.y * 128 * K;
    const __nv_bfloat16* Bhp = Bh + z * sB + blockIdx.x * 128;
    const __nv_bfloat16* Blp = Bl + z * sB + blockIdx.x * 128;

    float acc[4][4][4];
    for (int a = 0; a < 4; a++)
        for (int b = 0; b < 4; b++)
            for (int c = 0; c < 4; c++)
                acc[a][b][c] = 0.f;

    const int lm_row = lane & 15;          // 0..15
    const int lm_col = (lane >> 4) * 8;    // 0 or 8

    for (int k0 = 0; k0 < K; k0 += 32) {
        // A tiles: 128 rows x 32 cols, 16B chunks (512 chunks each of hi/lo)
        for (int c = tid; c < 512; c += 256) {
            int row = c >> 2;
            int col = (c & 3) * 8;
            long long gidx = (long long)row * K + k0 + col;
            *(uint4*)&sAh[row][col] = *(const uint4*)(Ahp + gidx);
            *(uint4*)&sAl[row][col] = *(const uint4*)(Alp + gidx);
        }
        // B tiles: 32 rows x 128 cols
        for (int c = tid; c < 512; c += 256) {
            int row = c >> 4;
            int col = (c & 15) * 8;
            long long gidx = (long long)(k0 + row) * N + col;
            *(uint4*)&sBh[row][col] = *(const uint4*)(Bhp + gidx);
            *(uint4*)&sBl[row][col] = *(const uint4*)(Blp + gidx);
        }
        __syncthreads();

        for (int kk = 0; kk < 2; kk++) {
            const int ks = kk * 16;
            unsigned int ahf[4][4], alf[4][4], bhf[4][2], blf[4][2];
            for (int mt = 0; mt < 4; mt++) {
                ldmat_x4(ahf[mt], &sAh[m_base + mt * 16 + lm_row][ks + lm_col]);
                ldmat_x4(alf[mt], &sAl[m_base + mt * 16 + lm_row][ks + lm_col]);
            }
            for (int ng = 0; ng < 2; ng++) {
                unsigned int t[4];
                ldmat_x4t(t, &sBh[ks + lm_row][n_base + ng * 16 + lm_col]);
                bhf[2 * ng][0]     = t[0];
                bhf[2 * ng][1]     = t[1];
                bhf[2 * ng + 1][0] = t[2];
                bhf[2 * ng + 1][1] = t[3];
                ldmat_x4t(t, &sBl[ks + lm_row][n_base + ng * 16 + lm_col]);
                blf[2 * ng][0]     = t[0];
                blf[2 * ng][1]     = t[1];
                blf[2 * ng + 1][0] = t[2];
                blf[2 * ng + 1][1] = t[3];
            }
            for (int mt = 0; mt < 4; mt++) {
                for (int nt = 0; nt < 4; nt++) {
                    mma16816(acc[mt][nt], ahf[mt], bhf[nt]);
                    mma16816(acc[mt][nt], ahf[mt], blf[nt]);
                    mma16816(acc[mt][nt], alf[mt], bhf[nt]);
                }
            }
        }
        __syncthreads();
    }

    // epilogue
    const int grp = lane >> 2;
    const int tq  = lane & 3;
    const long long crow0 = (long long)blockIdx.y * 128;
    const int ccol0 = blockIdx.x * 128;
    float* Cfp = Cf ? (Cf + z * sC) : (float*)0;
    __nv_bfloat16* Chp = Ch ? (Ch + z * sC) : (__nv_bfloat16*)0;
    __nv_bfloat16* Clp = Cl ? (Cl + z * sC) : (__nv_bfloat16*)0;

    for (int mt = 0; mt < 4; mt++) {
        for (int nt = 0; nt < 4; nt++) {
            int c = ccol0 + n_base + nt * 8 + 2 * tq;
            float b0 = bias ? bias[c] : 0.f;
            float b1 = bias ? bias[c + 1] : 0.f;
            for (int half = 0; half < 2; half++) {
                long long r = crow0 + m_base + mt * 16 + grp + half * 8;
                float v0 = acc[mt][nt][2 * half + 0] + b0;
                float v1 = acc[mt][nt][2 * half + 1] + b1;
                if (Cfp) {
                    float2 v;
                    v.x = v0; v.y = v1;
                    *(float2*)(Cfp + r * N + c) = v;
                }
                if (Chp) {
                    __nv_bfloat16 h0, h1, l0, l1;
                    split2(v0, h0, l0);
                    split2(v1, h1, l1);
                    __nv_bfloat162 p;
                    p.x = h0; p.y = h1;
                    *(__nv_bfloat162*)(Chp + r * N + c) = p;
                    p.x = l0; p.y = l1;
                    *(__nv_bfloat162*)(Clp + r * N + c) = p;
                }
            }
        }
    }
}

// ---------------------------------------------------------------------------
// fidelity kernel + interference + softmax -> attn (fp32) + bf16 hi/lo split
// ---------------------------------------------------------------------------
__global__ __launch_bounds__(256)
void attn_kernel(const float* __restrict__ phi, float* __restrict__ attn)
{
    int row = blockIdx.x;                 // b*512 + i
    int b = row >> 9;
    int i = row & 511;
    const float* st_b = g_states + (size_t)b * S_ * (Q_ * 4);

    __shared__ float si[Q_ * 4];
    __shared__ float sK[S_];
    __shared__ float scp[S_];
    __shared__ float ssp[S_];
    __shared__ float red[8];

    if (threadIdx.x < Q_ * 4)
        si[threadIdx.x] = st_b[(size_t)i * (Q_ * 4) + threadIdx.x];
    for (int j = threadIdx.x; j < S_; j += 256) {
        float p = phi[j];
        scp[j] = cosf(p);
        ssp[j] = sinf(p);
    }
    __syncthreads();

    float ci  = scp[i];
    float sii = ssp[i];

    for (int j = threadIdx.x; j < S_; j += 256) {
        const float* sj = st_b + (size_t)j * (Q_ * 4);
        float Kv = 1.f;
        for (int q = 0; q < Q_; q++) {
            float air = si[q * 4 + 0], aii = si[q * 4 + 1];
            float bir = si[q * 4 + 2], bii = si[q * 4 + 3];
            float ajr = sj[q * 4 + 0], aji = sj[q * 4 + 1];
            float bjr = sj[q * 4 + 2], bji = sj[q * 4 + 3];
            float re = air * ajr + aii * aji + bir * bjr + bii * bji;
            float im = air * aji - aii * ajr + bir * bji - bii * bjr;
            Kv *= re * re + im * im;
        }
        sK[j] = Kv + ci * scp[j] + sii * ssp[j];   // + cos(phi_i - phi_j)
    }
    __syncthreads();

    // row max
    float m = -1e30f;
    for (int j = threadIdx.x; j < S_; j += 256)
        m = fmaxf(m, sK[j]);
    for (int off = 16; off; off >>= 1)
        m = fmaxf(m, __shfl_xor_sync(0xffffffffu, m, off));
    if ((threadIdx.x & 31) == 0)
        red[threadIdx.x >> 5] = m;
    __syncthreads();
    if (threadIdx.x < 8) {
        float v = red[threadIdx.x];
        for (int off = 4; off; off >>= 1)
            v = fmaxf(v, __shfl_xor_sync(0xffu, v, off));
        if (threadIdx.x == 0) red[0] = v;
    }
    __syncthreads();
    m = red[0];
    __syncthreads();

    // exp + sum
    float sum = 0.f;
    for (int j = threadIdx.x; j < S_; j += 256) {
        float e = expf(sK[j] - m);
        sK[j] = e;
        sum += e;
    }
    for (int off = 16; off; off >>= 1)
        sum += __shfl_xor_sync(0xffffffffu, sum, off);
    if ((threadIdx.x & 31) == 0)
        red[threadIdx.x >> 5] = sum;
    __syncthreads();
    if (threadIdx.x < 8) {
        float v = red[threadIdx.x];
        for (int off = 4; off; off >>= 1)
            v += __shfl_xor_sync(0xffu, v, off);
        if (threadIdx.x == 0) red[0] = v;
    }
    __syncthreads();
    float inv = 1.f / red[0];

    float* arow = attn + (size_t)row * S_;
    __nv_bfloat16* hrow = g_Ath + (size_t)row * S_;
    __nv_bfloat16* lrow = g_Atl + (size_t)row * S_;
    for (int j = threadIdx.x; j < S_; j += 256) {
        float v = sK[j] * inv;
        arow[j] = v;
        __nv_bfloat16 h, l;
        split2(v, h, l);
        hrow[j] = h;
        lrow[j] = l;
    }
}

// ---------------------------------------------------------------------------
// launch
// ---------------------------------------------------------------------------
extern "C" void kernel_launch(void* const* d_in, const int* in_sizes, int n_in,
                              void* d_out, int out_size)
{
    const float* X     = (const float*)d_in[0];
    const float* Wq    = (const float*)d_in[1];
    const float* bq    = (const float*)d_in[2];
    const float* Wv    = (const float*)d_in[3];
    const float* bv    = (const float*)d_in[4];
    const float* Wo    = (const float*)d_in[5];
    const float* bo    = (const float*)d_in[6];
    const float* theta = (const float*)d_in[7];
    const float* phi   = (const float*)d_in[8];

    float* out  = (float*)d_out;                 // [B,S,E]
    float* attn = (float*)d_out + OUT_ELEMS;     // [B,S,S]

    (void)in_sizes;
    (void)n_in;
    (void)out_size;

    __nv_bfloat16 *Xh, *Xl, *Wvh, *Wvl, *Woh, *Wol, *Vh, *Vl, *Ath, *Atl, *Th, *Tl;
    cudaGetSymbolAddress((void**)&Xh,  g_Xh);
    cudaGetSymbolAddress((void**)&Xl,  g_Xl);
    cudaGetSymbolAddress((void**)&Wvh, g_Wvh);
    cudaGetSymbolAddress((void**)&Wvl, g_Wvl);
    cudaGetSymbolAddress((void**)&Woh, g_Woh);
    cudaGetSymbolAddress((void**)&Wol, g_Wol);
    cudaGetSymbolAddress((void**)&Vh,  g_Vh);
    cudaGetSymbolAddress((void**)&Vl,  g_Vl);
    cudaGetSymbolAddress((void**)&Ath, g_Ath);
    cudaGetSymbolAddress((void**)&Atl, g_Atl);
    cudaGetSymbolAddress((void**)&Th,  g_Th);
    cudaGetSymbolAddress((void**)&Tl,  g_Tl);

    // input splits
    split_fp32_kernel<<<(BS_ROWS * E_ / 4 + 255) / 256, 256>>>(X, Xh, Xl, BS_ROWS * E_);
    split_fp32_kernel<<<(E_ * E_ / 4 + 255) / 256, 256>>>(Wv, Wvh, Wvl, E_ * E_);
    split_fp32_kernel<<<(E_ * E_ / 4 + 255) / 256, 256>>>(Wo, Woh, Wol, E_ * E_);

    // 1) qubit states
    qstate_kernel<<<BS_ROWS, 256>>>(X, Wq, bq, theta);

    // 2) V = X @ Wv + bv  -> bf16 split (Vh, Vl)
    {
        dim3 grid(E_ / 128, BS_ROWS / 128, 1);
        gemm_bf16s<<<grid, 256>>>(Xh, Xl, Wvh, Wvl, bv,
                                  (float*)0, Vh, Vl,
                                  BS_ROWS, E_, E_, 0, 0, 0);
    }

    // 3) kernel matrix + softmax -> attn fp32 (d_out) + bf16 split
    attn_kernel<<<BS_ROWS, 256>>>(phi, attn);

    // 4) T[b] = attn[b] @ V[b] -> bf16 split (Th, Tl)
    {
        dim3 grid(E_ / 128, S_ / 128, B_);
        gemm_bf16s<<<grid, 256>>>(Ath, Atl, Vh, Vl, (const float*)0,
                                  (float*)0, Th, Tl,
                                  S_, E_, S_,
                                  (long long)S_ * S_,
                                  (long long)S_ * E_,
                                  (long long)S_ * E_);
    }

    // 5) out = T @ Wo + bo  (fp32)
    {
        dim3 grid(E_ / 128, BS_ROWS / 128, 1);
        gemm_bf16s<<<grid, 256>>>(Th, Tl, Woh, Wol, bo,
                                  out, (__nv_bfloat16*)0, (__nv_bfloat16*)0,
                                  BS_ROWS, E_, E_, 0, 0, 0);
    }
}

// round 4
// speedup vs baseline: 2.8821x; 1.1749x over previous
#include <cuda_runtime.h>
#include <cuda_bf16.h>
#include <stdint.h>
#include <math.h>

// Problem shapes (fixed per reference)
#define B_ 16
#define S_ 512
#define E_ 1024
#define Q_ 8
#define L_ 4

#define BS_ROWS (B_ * S_)            // 8192
#define OUT_ELEMS (B_ * S_ * E_)     // 8388608
#define ATTN_ELEMS (B_ * S_ * S_)    // 4194304

// ---------------------------------------------------------------------------
// Scratch (device globals: allocation-free rule). 16B-aligned for uint4 I/O.
// ---------------------------------------------------------------------------
__device__ __align__(16) float g_states[BS_ROWS * Q_ * 4];

__device__ __align__(16) __nv_bfloat16 g_Xh[BS_ROWS * E_];
__device__ __align__(16) __nv_bfloat16 g_Xl[BS_ROWS * E_];
__device__ __align__(16) __nv_bfloat16 g_Wvh[E_ * E_];
__device__ __align__(16) __nv_bfloat16 g_Wvl[E_ * E_];
__device__ __align__(16) __nv_bfloat16 g_Woh[E_ * E_];
__device__ __align__(16) __nv_bfloat16 g_Wol[E_ * E_];
__device__ __align__(16) __nv_bfloat16 g_Vh[B_ * S_ * E_];
__device__ __align__(16) __nv_bfloat16 g_Vl[B_ * S_ * E_];
__device__ __align__(16) __nv_bfloat16 g_Ath[B_ * S_ * S_];
__device__ __align__(16) __nv_bfloat16 g_Atl[B_ * S_ * S_];
__device__ __align__(16) __nv_bfloat16 g_Th[B_ * S_ * E_];
__device__ __align__(16) __nv_bfloat16 g_Tl[B_ * S_ * E_];

__device__ __forceinline__ void split2(float v, __nv_bfloat16 &h, __nv_bfloat16 &l)
{
    h = __float2bfloat16(v);
    l = __float2bfloat16(v - __bfloat162float(h));
}

// ---------------------------------------------------------------------------
// Split fp32 -> bf16 hi/lo (vectorized) — used for Wv, Wo only
// ---------------------------------------------------------------------------
__global__ void split_fp32_kernel(const float* __restrict__ src,
                                  __nv_bfloat16* __restrict__ h,
                                  __nv_bfloat16* __restrict__ l, int n)
{
    int i = (blockIdx.x * blockDim.x + threadIdx.x) * 4;
    if (i >= n) return;
    float4 v = *(const float4*)(src + i);
    __nv_bfloat16 h0, h1, h2, h3, l0, l1, l2, l3;
    split2(v.x, h0, l0);
    split2(v.y, h1, l1);
    split2(v.z, h2, l2);
    split2(v.w, h3, l3);
    __nv_bfloat162 p;
    p.x = h0; p.y = h1; *(__nv_bfloat162*)(h + i)     = p;
    p.x = h2; p.y = h3; *(__nv_bfloat162*)(h + i + 2) = p;
    p.x = l0; p.y = l1; *(__nv_bfloat162*)(l + i)     = p;
    p.x = l2; p.y = l3; *(__nv_bfloat162*)(l + i + 2) = p;
}

// ---------------------------------------------------------------------------
// Kernel 1: fused  (a) X bf16 hi/lo split,
//                  (b) quantum_input = X@Wq + bq,
//                  (c) RY/RZ recursion -> product state
// One warp per row (8 rows / 256-thread block). Wq transposed in smem.
// ---------------------------------------------------------------------------
__global__ __launch_bounds__(256)
void qsplit_kernel(const float* __restrict__ X,
                   const float* __restrict__ Wq,
                   const float* __restrict__ bq,
                   const float* __restrict__ theta,
                   __nv_bfloat16* __restrict__ Xh,
                   __nv_bfloat16* __restrict__ Xl)
{
    __shared__ float sWq[Q_][E_];   // 32 KB, transposed: sWq[q][e]

    const int tid  = threadIdx.x;
    const int warp = tid >> 5;
    const int lane = tid & 31;

    for (int idx = tid; idx < E_ * Q_; idx += 256) {
        int e = idx >> 3;
        int q = idx & 7;
        sWq[q][e] = Wq[idx];
    }
    __syncthreads();

    const int row = blockIdx.x * 8 + warp;
    const float* x = X + (size_t)row * E_;
    __nv_bfloat16* xh = Xh + (size_t)row * E_;
    __nv_bfloat16* xl = Xl + (size_t)row * E_;

    float acc[Q_];
    for (int q = 0; q < Q_; q++) acc[q] = 0.f;

    for (int e = lane; e < E_; e += 32) {
        float xv = x[e];
        __nv_bfloat16 h, l;
        split2(xv, h, l);
        xh[e] = h;
        xl[e] = l;
        #pragma unroll
        for (int q = 0; q < Q_; q++)
            acc[q] += xv * sWq[q][e];
    }
    #pragma unroll
    for (int q = 0; q < Q_; q++)
        for (int off = 16; off; off >>= 1)
            acc[q] += __shfl_xor_sync(0xffffffffu, acc[q], off);

    if (lane < Q_) {
        int q = lane;
        float ang = acc[q] + bq[q];
        float ar = cosf(0.5f * ang);
        float ai = 0.f;
        float br = sinf(0.5f * ang);
        float bi = 0.f;
        for (int l = 0; l < L_; l++) {
            float t0 = 0.5f * theta[(l * Q_ + q) * 2 + 0];
            float t1 = 0.5f * theta[(l * Q_ + q) * 2 + 1];
            float c = cosf(t0), s = sinf(t0);
            float nar = c * ar - s * br, nai = c * ai - s * bi;
            float nbr = s * ar + c * br, nbi = s * ai + c * bi;
            float cp = cosf(t1), sp = sinf(t1);
            ar = nar * cp + nai * sp;
            ai = nai * cp - nar * sp;
            br = nbr * cp - nbi * sp;
            bi = nbi * cp + nbr * sp;
        }
        float* st = g_states + (size_t)row * (Q_ * 4) + q * 4;
        st[0] = ar; st[1] = ai; st[2] = br; st[3] = bi;
    }
}

// ---------------------------------------------------------------------------
// mma.sync / cp.async helpers
// ---------------------------------------------------------------------------
__device__ __forceinline__ void ldmat_x4(unsigned int* r, const __nv_bfloat16* p)
{
    unsigned int a = (unsigned int)__cvta_generic_to_shared(p);
    asm volatile("ldmatrix.sync.aligned.m8n8.x4.shared.b16 {%0,%1,%2,%3}, [%4];"
                 : "=r"(r[0]), "=r"(r[1]), "=r"(r[2]), "=r"(r[3]) : "r"(a));
}

__device__ __forceinline__ void ldmat_x4t(unsigned int* r, const __nv_bfloat16* p)
{
    unsigned int a = (unsigned int)__cvta_generic_to_shared(p);
    asm volatile("ldmatrix.sync.aligned.m8n8.x4.trans.shared.b16 {%0,%1,%2,%3}, [%4];"
                 : "=r"(r[0]), "=r"(r[1]), "=r"(r[2]), "=r"(r[3]) : "r"(a));
}

__device__ __forceinline__ void mma16816(float* d, const unsigned int* a, const unsigned int* b)
{
    asm volatile(
        "mma.sync.aligned.m16n8k16.row.col.f32.bf16.bf16.f32 "
        "{%0,%1,%2,%3}, {%4,%5,%6,%7}, {%8,%9}, {%0,%1,%2,%3};"
        : "+f"(d[0]), "+f"(d[1]), "+f"(d[2]), "+f"(d[3])
        : "r"(a[0]), "r"(a[1]), "r"(a[2]), "r"(a[3]), "r"(b[0]), "r"(b[1]));
}

__device__ __forceinline__ void cp16(__nv_bfloat16* dst, const __nv_bfloat16* src)
{
    unsigned int d = (unsigned int)__cvta_generic_to_shared(dst);
    asm volatile("cp.async.cg.shared.global [%0], [%1], 16;" :: "r"(d), "l"(src));
}
__device__ __forceinline__ void cp_commit()
{
    asm volatile("cp.async.commit_group;");
}
template <int N>
__device__ __forceinline__ void cp_wait()
{
    asm volatile("cp.async.wait_group %0;" :: "n"(N));
}

// ---------------------------------------------------------------------------
// bf16-split GEMM, cp.async double-buffered.
// C = (Ah+Al)(Bh+Bl) ~= AhBh + AhBl + AlBh
// A row-major [M,K], B row-major [K,N]. 128x128x32 tile, 256 thr (8 warps).
// Dynamic smem: [Ah0 Ah1 Al0 Al1 Bh0 Bh1 Bl0 Bl1]
// ---------------------------------------------------------------------------
#define A_SZ (128 * 40)
#define B_SZ (32 * 136)
#define GEMM_SMEM_BYTES ((4 * A_SZ + 4 * B_SZ) * 2)

extern __shared__ __nv_bfloat16 g_dyn[];

__global__ __launch_bounds__(256)
void gemm_bf16s(const __nv_bfloat16* __restrict__ Ah, const __nv_bfloat16* __restrict__ Al,
                const __nv_bfloat16* __restrict__ Bh, const __nv_bfloat16* __restrict__ Bl,
                const float* __restrict__ bias,
                float* __restrict__ Cf,
                __nv_bfloat16* __restrict__ Ch, __nv_bfloat16* __restrict__ Cl,
                int M, int N, int K,
                long long sA, long long sB, long long sC)
{
    __nv_bfloat16* smAh[2];
    __nv_bfloat16* smAl[2];
    __nv_bfloat16* smBh[2];
    __nv_bfloat16* smBl[2];
    smAh[0] = g_dyn;
    smAh[1] = g_dyn + A_SZ;
    smAl[0] = g_dyn + 2 * A_SZ;
    smAl[1] = g_dyn + 3 * A_SZ;
    smBh[0] = g_dyn + 4 * A_SZ;
    smBh[1] = g_dyn + 4 * A_SZ + B_SZ;
    smBl[0] = g_dyn + 4 * A_SZ + 2 * B_SZ;
    smBl[1] = g_dyn + 4 * A_SZ + 3 * B_SZ;

    const int tid  = threadIdx.x;
    const int warp = tid >> 5;
    const int lane = tid & 31;
    const int warp_m = warp & 1;           // 2 x 4 warp grid
    const int warp_n = warp >> 1;
    const int m_base = warp_m * 64;
    const int n_base = warp_n * 32;

    const long long z = blockIdx.z;
    const __nv_bfloat16* Ahp = Ah + z * sA + (long long)blockIdx.y * 128 * K;
    const __nv_bfloat16* Alp = Al + z * sA + (long long)blockIdx.y * 128 * K;
    const __nv_bfloat16* Bhp = Bh + z * sB + blockIdx.x * 128;
    const __nv_bfloat16* Blp = Bl + z * sB + blockIdx.x * 128;

    // per-thread fixed copy assignments (2 chunks of A-pair + 2 of B-pair)
    const int ar0 = tid >> 1, ac0 = (tid & 1) * 16;          // A rows 0..127, col 0/16 (+8 next)
    const int br0 = tid >> 4, bc0 = (tid & 15) * 8;          // B rows 0..15 (+16 next)

    float acc[4][4][4];
    for (int a = 0; a < 4; a++)
        for (int b = 0; b < 4; b++)
            for (int c = 0; c < 4; c++)
                acc[a][b][c] = 0.f;

    const int lm_row = lane & 15;
    const int lm_col = (lane >> 4) * 8;

    const int nIter = K / 32;

    // --- stage loader ---
    #define LOAD_STAGE(st, k0)                                                  \
    {                                                                           \
        long long ga = (long long)ar0 * K + (k0) + ac0;                         \
        cp16(smAh[st] + ar0 * 40 + ac0,     Ahp + ga);                          \
        cp16(smAh[st] + ar0 * 40 + ac0 + 8, Ahp + ga + 8);                      \
        cp16(smAl[st] + ar0 * 40 + ac0,     Alp + ga);                          \
        cp16(smAl[st] + ar0 * 40 + ac0 + 8, Alp + ga + 8);                      \
        long long gb0 = (long long)((k0) + br0) * N + bc0;                      \
        long long gb1 = (long long)((k0) + br0 + 16) * N + bc0;                 \
        cp16(smBh[st] + br0 * 136 + bc0,        Bhp + gb0);                     \
        cp16(smBh[st] + (br0 + 16) * 136 + bc0, Bhp + gb1);                     \
        cp16(smBl[st] + br0 * 136 + bc0,        Blp + gb0);                     \
        cp16(smBl[st] + (br0 + 16) * 136 + bc0, Blp + gb1);                     \
        cp_commit();                                                            \
    }

    LOAD_STAGE(0, 0);

    for (int it = 0; it < nIter; it++) {
        const int cur = it & 1;
        if (it + 1 < nIter) {
            LOAD_STAGE(cur ^ 1, (it + 1) * 32);
            cp_wait<1>();
        } else {
            cp_wait<0>();
        }
        __syncthreads();

        for (int kk = 0; kk < 2; kk++) {
            const int ks = kk * 16;
            unsigned int ahf[4][4], alf[4][4], bhf[4][2], blf[4][2];
            for (int mt = 0; mt < 4; mt++) {
                ldmat_x4(ahf[mt], smAh[cur] + (m_base + mt * 16 + lm_row) * 40 + ks + lm_col);
                ldmat_x4(alf[mt], smAl[cur] + (m_base + mt * 16 + lm_row) * 40 + ks + lm_col);
            }
            for (int ng = 0; ng < 2; ng++) {
                unsigned int t[4];
                ldmat_x4t(t, smBh[cur] + (ks + lm_row) * 136 + n_base + ng * 16 + lm_col);
                bhf[2 * ng][0]     = t[0];
                bhf[2 * ng][1]     = t[1];
                bhf[2 * ng + 1][0] = t[2];
                bhf[2 * ng + 1][1] = t[3];
                ldmat_x4t(t, smBl[cur] + (ks + lm_row) * 136 + n_base + ng * 16 + lm_col);
                blf[2 * ng][0]     = t[0];
                blf[2 * ng][1]     = t[1];
                blf[2 * ng + 1][0] = t[2];
                blf[2 * ng + 1][1] = t[3];
            }
            for (int mt = 0; mt < 4; mt++) {
                for (int nt = 0; nt < 4; nt++) {
                    mma16816(acc[mt][nt], ahf[mt], bhf[nt]);
                    mma16816(acc[mt][nt], ahf[mt], blf[nt]);
                    mma16816(acc[mt][nt], alf[mt], bhf[nt]);
                }
            }
        }
        __syncthreads();
    }

    // epilogue
    const int grp = lane >> 2;
    const int tq  = lane & 3;
    const long long crow0 = (long long)blockIdx.y * 128;
    const int ccol0 = blockIdx.x * 128;
    float* Cfp = Cf ? (Cf + z * sC) : (float*)0;
    __nv_bfloat16* Chp = Ch ? (Ch + z * sC) : (__nv_bfloat16*)0;
    __nv_bfloat16* Clp = Cl ? (Cl + z * sC) : (__nv_bfloat16*)0;

    for (int mt = 0; mt < 4; mt++) {
        for (int nt = 0; nt < 4; nt++) {
            int c = ccol0 + n_base + nt * 8 + 2 * tq;
            float b0 = bias ? bias[c] : 0.f;
            float b1 = bias ? bias[c + 1] : 0.f;
            for (int half = 0; half < 2; half++) {
                long long r = crow0 + m_base + mt * 16 + grp + half * 8;
                float v0 = acc[mt][nt][2 * half + 0] + b0;
                float v1 = acc[mt][nt][2 * half + 1] + b1;
                if (Cfp) {
                    float2 v;
                    v.x = v0; v.y = v1;
                    *(float2*)(Cfp + r * N + c) = v;
                }
                if (Chp) {
                    __nv_bfloat16 h0, h1, l0, l1;
                    split2(v0, h0, l0);
                    split2(v1, h1, l1);
                    __nv_bfloat162 p;
                    p.x = h0; p.y = h1;
                    *(__nv_bfloat162*)(Chp + r * N + c) = p;
                    p.x = l0; p.y = l1;
                    *(__nv_bfloat162*)(Clp + r * N + c) = p;
                }
            }
        }
    }
}

// ---------------------------------------------------------------------------
// fidelity kernel + interference + softmax -> attn (fp32) + bf16 hi/lo split
// ---------------------------------------------------------------------------
__global__ __launch_bounds__(256)
void attn_kernel(const float* __restrict__ phi, float* __restrict__ attn)
{
    int row = blockIdx.x;                 // b*512 + i
    int b = row >> 9;
    int i = row & 511;
    const float* st_b = g_states + (size_t)b * S_ * (Q_ * 4);

    __shared__ float si[Q_ * 4];
    __shared__ float sK[S_];
    __shared__ float scp[S_];
    __shared__ float ssp[S_];
    __shared__ float red[8];

    if (threadIdx.x < Q_ * 4)
        si[threadIdx.x] = st_b[(size_t)i * (Q_ * 4) + threadIdx.x];
    for (int j = threadIdx.x; j < S_; j += 256) {
        float p = phi[j];
        scp[j] = cosf(p);
        ssp[j] = sinf(p);
    }
    __syncthreads();

    float ci  = scp[i];
    float sii = ssp[i];

    for (int j = threadIdx.x; j < S_; j += 256) {
        const float* sj = st_b + (size_t)j * (Q_ * 4);
        float Kv = 1.f;
        for (int q = 0; q < Q_; q++) {
            float air = si[q * 4 + 0], aii = si[q * 4 + 1];
            float bir = si[q * 4 + 2], bii = si[q * 4 + 3];
            float ajr = sj[q * 4 + 0], aji = sj[q * 4 + 1];
            float bjr = sj[q * 4 + 2], bji = sj[q * 4 + 3];
            float re = air * ajr + aii * aji + bir * bjr + bii * bji;
            float im = air * aji - aii * ajr + bir * bji - bii * bjr;
            Kv *= re * re + im * im;
        }
        sK[j] = Kv + ci * scp[j] + sii * ssp[j];   // + cos(phi_i - phi_j)
    }
    __syncthreads();

    float m = -1e30f;
    for (int j = threadIdx.x; j < S_; j += 256)
        m = fmaxf(m, sK[j]);
    for (int off = 16; off; off >>= 1)
        m = fmaxf(m, __shfl_xor_sync(0xffffffffu, m, off));
    if ((threadIdx.x & 31) == 0)
        red[threadIdx.x >> 5] = m;
    __syncthreads();
    if (threadIdx.x < 8) {
        float v = red[threadIdx.x];
        for (int off = 4; off; off >>= 1)
            v = fmaxf(v, __shfl_xor_sync(0xffu, v, off));
        if (threadIdx.x == 0) red[0] = v;
    }
    __syncthreads();
    m = red[0];
    __syncthreads();

    float sum = 0.f;
    for (int j = threadIdx.x; j < S_; j += 256) {
        float e = expf(sK[j] - m);
        sK[j] = e;
        sum += e;
    }
    for (int off = 16; off; off >>= 1)
        sum += __shfl_xor_sync(0xffffffffu, sum, off);
    if ((threadIdx.x & 31) == 0)
        red[threadIdx.x >> 5] = sum;
    __syncthreads();
    if (threadIdx.x < 8) {
        float v = red[threadIdx.x];
        for (int off = 4; off; off >>= 1)
            v += __shfl_xor_sync(0xffu, v, off);
        if (threadIdx.x == 0) red[0] = v;
    }
    __syncthreads();
    float inv = 1.f / red[0];

    float* arow = attn + (size_t)row * S_;
    __nv_bfloat16* hrow = g_Ath + (size_t)row * S_;
    __nv_bfloat16* lrow = g_Atl + (size_t)row * S_;
    for (int j = threadIdx.x; j < S_; j += 256) {
        float v = sK[j] * inv;
        arow[j] = v;
        __nv_bfloat16 h, l;
        split2(v, h, l);
        hrow[j] = h;
        lrow[j] = l;
    }
}

// ---------------------------------------------------------------------------
// launch
// ---------------------------------------------------------------------------
extern "C" void kernel_launch(void* const* d_in, const int* in_sizes, int n_in,
                              void* d_out, int out_size)
{
    const float* X     = (const float*)d_in[0];
    const float* Wq    = (const float*)d_in[1];
    const float* bq    = (const float*)d_in[2];
    const float* Wv    = (const float*)d_in[3];
    const float* bv    = (const float*)d_in[4];
    const float* Wo    = (const float*)d_in[5];
    const float* bo    = (const float*)d_in[6];
    const float* theta = (const float*)d_in[7];
    const float* phi   = (const float*)d_in[8];

    float* out  = (float*)d_out;                 // [B,S,E]
    float* attn = (float*)d_out + OUT_ELEMS;     // [B,S,S]

    (void)in_sizes;
    (void)n_in;
    (void)out_size;

    __nv_bfloat16 *Xh, *Xl, *Wvh, *Wvl, *Woh, *Wol, *Vh, *Vl, *Ath, *Atl, *Th, *Tl;
    cudaGetSymbolAddress((void**)&Xh,  g_Xh);
    cudaGetSymbolAddress((void**)&Xl,  g_Xl);
    cudaGetSymbolAddress((void**)&Wvh, g_Wvh);
    cudaGetSymbolAddress((void**)&Wvl, g_Wvl);
    cudaGetSymbolAddress((void**)&Woh, g_Woh);
    cudaGetSymbolAddress((void**)&Wol, g_Wol);
    cudaGetSymbolAddress((void**)&Vh,  g_Vh);
    cudaGetSymbolAddress((void**)&Vl,  g_Vl);
    cudaGetSymbolAddress((void**)&Ath, g_Ath);
    cudaGetSymbolAddress((void**)&Atl, g_Atl);
    cudaGetSymbolAddress((void**)&Th,  g_Th);
    cudaGetSymbolAddress((void**)&Tl,  g_Tl);

    static int s_attr_done = 0;
    if (!s_attr_done) {
        cudaFuncSetAttribute(gemm_bf16s,
                             cudaFuncAttributeMaxDynamicSharedMemorySize,
                             GEMM_SMEM_BYTES);
        s_attr_done = 1;
    }

    // weight splits
    split_fp32_kernel<<<(E_ * E_ / 4 + 255) / 256, 256>>>(Wv, Wvh, Wvl, E_ * E_);
    split_fp32_kernel<<<(E_ * E_ / 4 + 255) / 256, 256>>>(Wo, Woh, Wol, E_ * E_);

    // 1) fused X split + qubit states
    qsplit_kernel<<<BS_ROWS / 8, 256>>>(X, Wq, bq, theta, Xh, Xl);

    // 2) V = X @ Wv + bv  -> bf16 split (Vh, Vl)
    {
        dim3 grid(E_ / 128, BS_ROWS / 128, 1);
        gemm_bf16s<<<grid, 256, GEMM_SMEM_BYTES>>>(Xh, Xl, Wvh, Wvl, bv,
                                                   (float*)0, Vh, Vl,
                                                   BS_ROWS, E_, E_, 0, 0, 0);
    }

    // 3) kernel matrix + softmax -> attn fp32 (d_out) + bf16 split
    attn_kernel<<<BS_ROWS, 256>>>(phi, attn);

    // 4) T[b] = attn[b] @ V[b] -> bf16 split (Th, Tl)
    {
        dim3 grid(E_ / 128, S_ / 128, B_);
        gemm_bf16s<<<grid, 256, GEMM_SMEM_BYTES>>>(Ath, Atl, Vh, Vl, (const float*)0,
                                                   (float*)0, Th, Tl,
                                                   S_, E_, S_,
                                                   (long long)S_ * S_,
                                                   (long long)S_ * E_,
                                                   (long long)S_ * E_);
    }

    // 5) out = T @ Wo + bo  (fp32)
    {
        dim3 grid(E_ / 128, BS_ROWS / 128, 1);
        gemm_bf16s<<<grid, 256, GEMM_SMEM_BYTES>>>(Th, Tl, Woh, Wol, bo,
                                                   out, (__nv_bfloat16*)0, (__nv_bfloat16*)0,
                                                   BS_ROWS, E_, E_, 0, 0, 0);
    }
}